// round 17
// baseline (speedup 1.0000x reference)
#include <cuda_runtime.h>
#include <cuda_bf16.h>
#include <cuda_fp16.h>
#include <math.h>
#include <stdint.h>

// Problem constants
#define Bsz 8
#define Tlen 1024
#define IN_DIM 32
#define HID 512
#define DI 1024
#define DS 16
#define DTR 32
#define Fdim 96
#define MT (Bsz * Tlen)   // 8192 rows

// ---------------- scratch (device globals; no runtime allocation) ----------------
__device__ float g_h[MT * HID];
__device__ __half g_hn_h[MT * HID];
__device__ __half g_xz_h[MT * 2 * DI];     // fp16 xz (x | z)
__device__ __half g_xssm_h[MT * DI];
__device__ float g_dbl[MT * 64];
__device__ __half g_dbl_h[MT * 64];
__device__ float g_delta[MT * DI];
__device__ __half g_y_h[MT * DI];
__device__ __half g_wi_h[2 * 2 * DI * HID];
__device__ __half g_wo_h[2 * HID * DI];
__device__ __half g_xpw_h[2 * 64 * DI];
__device__ __half g_dpw_h[2 * DI * DTR];

__device__ __forceinline__ uint32_t smem_u32(const void* p) {
    uint32_t a;
    asm("{ .reg .u64 t; cvta.to.shared.u64 t, %1; cvt.u32.u64 %0, t; }" : "=r"(a) : "l"(p));
    return a;
}

__device__ __forceinline__ void cpa16(uint32_t saddr, const void* gaddr) {
    asm volatile("cp.async.cg.shared.global [%0], [%1], 16;" :: "r"(saddr), "l"(gaddr));
}

// ---------------- fused fp32 -> fp16 conversion of all 4 weight groups ----------------
#define N_WI (2 * 2 * DI * HID)
#define N_WO (2 * HID * DI)
#define N_XPW (2 * 64 * DI)
#define N_DPW (2 * DI * DTR)
#define N_ALLW (N_WI + N_WO + N_XPW + N_DPW)

__global__ void f2h_all_kernel(const float* __restrict__ wi, const float* __restrict__ wo,
                               const float* __restrict__ xpw, const float* __restrict__ dpw,
                               __half* __restrict__ wi_h, __half* __restrict__ wo_h,
                               __half* __restrict__ xpw_h, __half* __restrict__ dpw_h) {
    int i = blockIdx.x * blockDim.x + threadIdx.x;
    if (i < N_WI) { wi_h[i] = __float2half(wi[i]); return; }
    i -= N_WI;
    if (i < N_WO) { wo_h[i] = __float2half(wo[i]); return; }
    i -= N_WO;
    if (i < N_XPW) { xpw_h[i] = __float2half(xpw[i]); return; }
    i -= N_XPW;
    if (i < N_DPW) { dpw_h[i] = __float2half(dpw[i]); }
}

__device__ __forceinline__ void mma16(float* d, const uint32_t* a, const uint32_t* b) {
    asm volatile(
        "mma.sync.aligned.m16n8k16.row.col.f32.f16.f16.f32 "
        "{%0,%1,%2,%3}, {%4,%5,%6,%7}, {%8,%9}, {%0,%1,%2,%3};"
        : "+f"(d[0]), "+f"(d[1]), "+f"(d[2]), "+f"(d[3])
        : "r"(a[0]), "r"(a[1]), "r"(a[2]), "r"(a[3]), "r"(b[0]), "r"(b[1]));
}

__device__ __forceinline__ void ldsm4(uint32_t& r0, uint32_t& r1, uint32_t& r2, uint32_t& r3,
                                      uint32_t addr) {
    asm volatile("ldmatrix.sync.aligned.m8n8.x4.shared.b16 {%0,%1,%2,%3}, [%4];"
                 : "=r"(r0), "=r"(r1), "=r"(r2), "=r"(r3) : "r"(addr));
}

// ================= main fp16 GEMM v2: 512 threads, 16 warps (4m x 4n), wt 32x32 =====
// CTA tile 128x128x64, ldmatrix operand fetch, 2-stage cp.async pipeline.
// MODE 0: fp16 output to Ch ; MODE 1: fp32 residual add into C.

#define H2PAD 72
#define H2TILE (128 * H2PAD)
#define H2STAGE (2 * H2TILE)
#define H2SMEM_BYTES (2 * H2STAGE * 2)   // 73728 B (2 stages)

__device__ __forceinline__ void load_tile64w(const __half* __restrict__ g, int ld,
                                             int row0, int k0, __half* s, int tid) {
#pragma unroll
    for (int i = 0; i < 2; i++) {
        int flat = i * 512 + tid;
        int r = flat >> 3;
        int c = flat & 7;
        const __half* gp = g + (size_t)(row0 + r) * ld + k0 + c * 8;
        cpa16(smem_u32(s + r * H2PAD + c * 8), gp);
    }
}

template<int MODE>
__global__ void __launch_bounds__(512, 2)
gemm_hmma64_kernel(const __half* __restrict__ A, int lda,
                   const __half* __restrict__ B, int ldb,
                   float* __restrict__ C, __half* __restrict__ Ch, int ldc, int K)
{
    extern __shared__ __half smh[];
    int tid = threadIdx.x;
    int wid = tid >> 5, lane = tid & 31;
    int g = lane >> 2, t = lane & 3;
    int warp_m = wid >> 2;      // 0..3 -> 32 rows each
    int warp_n = wid & 3;       // 0..3 -> 32 cols each
    int bm = blockIdx.y * 128;
    int bn = blockIdx.x * 128;

    int q = lane >> 3, li = lane & 7;
    int lrow = ((q & 1) << 3) + li;
    int lcol = (q >> 1) << 3;

    float acc[2][4][4];
#pragma unroll
    for (int mt = 0; mt < 2; mt++)
#pragma unroll
        for (int nt = 0; nt < 4; nt++)
#pragma unroll
            for (int qq = 0; qq < 4; qq++) acc[mt][nt][qq] = 0.f;

    int nk = K >> 6;

    load_tile64w(A, lda, bm, 0, smh, tid);
    load_tile64w(B, ldb, bn, 0, smh + H2TILE, tid);
    asm volatile("cp.async.commit_group;" ::: "memory");

    for (int kc = 0; kc < nk; kc++) {
        int buf = kc & 1;
        if (kc + 1 < nk) {
            int nb = 1 - buf;
            load_tile64w(A, lda, bm, (kc + 1) * 64, smh + nb * H2STAGE, tid);
            load_tile64w(B, ldb, bn, (kc + 1) * 64, smh + nb * H2STAGE + H2TILE, tid);
            asm volatile("cp.async.commit_group;" ::: "memory");
            asm volatile("cp.async.wait_group 1;" ::: "memory");
        } else {
            asm volatile("cp.async.wait_group 0;" ::: "memory");
        }
        __syncthreads();

        const __half* sA = smh + buf * H2STAGE;
        const __half* sB = sA + H2TILE;

        uint32_t aAddr[2], bAddr[2];
#pragma unroll
        for (int mt = 0; mt < 2; mt++)
            aAddr[mt] = smem_u32(&sA[(warp_m * 32 + mt * 16 + lrow) * H2PAD + lcol]);
#pragma unroll
        for (int p = 0; p < 2; p++)
            bAddr[p] = smem_u32(&sB[(warp_n * 32 + p * 16 + lrow) * H2PAD + lcol]);

#pragma unroll
        for (int kk = 0; kk < 64; kk += 16) {
            uint32_t afr[2][4];
#pragma unroll
            for (int mt = 0; mt < 2; mt++)
                ldsm4(afr[mt][0], afr[mt][1], afr[mt][2], afr[mt][3], aAddr[mt] + kk * 2);
            uint32_t bfr[4][2];
#pragma unroll
            for (int p = 0; p < 2; p++) {
                uint32_t r0, r1, r2, r3;
                ldsm4(r0, r1, r2, r3, bAddr[p] + kk * 2);
                bfr[2 * p][0] = r0; bfr[2 * p + 1][0] = r1;
                bfr[2 * p][1] = r2; bfr[2 * p + 1][1] = r3;
            }
#pragma unroll
            for (int mt = 0; mt < 2; mt++)
#pragma unroll
                for (int nt = 0; nt < 4; nt++)
                    mma16(acc[mt][nt], afr[mt], bfr[nt]);
        }
        __syncthreads();
    }

#pragma unroll
    for (int mt = 0; mt < 2; mt++) {
        int row = bm + warp_m * 32 + mt * 16 + g;
#pragma unroll
        for (int nt = 0; nt < 4; nt++) {
            int col = bn + warp_n * 32 + nt * 8 + t * 2;
            if (MODE == 0) {
                __half2 h0 = __floats2half2_rn(acc[mt][nt][0], acc[mt][nt][1]);
                __half2 h1 = __floats2half2_rn(acc[mt][nt][2], acc[mt][nt][3]);
                *(__half2*)(Ch + (size_t)row * ldc + col) = h0;
                *(__half2*)(Ch + (size_t)(row + 8) * ldc + col) = h1;
            } else {
                float* c0 = C + (size_t)row * ldc + col;
                float* c1 = C + (size_t)(row + 8) * ldc + col;
                float2 o0 = *(const float2*)c0;
                float2 o1 = *(const float2*)c1;
                *(float2*)c0 = make_float2(acc[mt][nt][0] + o0.x, acc[mt][nt][1] + o0.y);
                *(float2*)c1 = make_float2(acc[mt][nt][2] + o1.x, acc[mt][nt][3] + o1.y);
            }
        }
    }
}

// ================= dtproj fp16 GEMM (K=32, softplus epilogue) =======================
#define HPAD 40
#define HTILE (128 * HPAD)
#define HSTAGE (2 * HTILE)
#define HSMEM_BYTES (2 * HSTAGE * 2)

__device__ __forceinline__ void load_tileH(const __half* __restrict__ g, int ld,
                                           int row0, int k0, __half* s, int tid) {
#pragma unroll
    for (int i = 0; i < 2; i++) {
        int flat = i * 256 + tid;
        int r = flat >> 2;
        int c = flat & 3;
        const __half* gp = g + (size_t)(row0 + r) * ld + k0 + c * 8;
        cpa16(smem_u32(s + r * HPAD + c * 8), gp);
    }
}

__global__ void __launch_bounds__(256)
gemm_dtproj_kernel(const __half* __restrict__ A, int lda,
                   const __half* __restrict__ B, int ldb,
                   const float* __restrict__ bias,
                   float* __restrict__ C, int ldc)
{
    extern __shared__ __half smh[];
    int tid = threadIdx.x;
    int wid = tid >> 5, lane = tid & 31;
    int g = lane >> 2, t = lane & 3;
    int warp_m = wid >> 2;
    int warp_n = wid & 3;
    int bm = blockIdx.y * 128;
    int bn = blockIdx.x * 128;

    float acc[4][4][4];
#pragma unroll
    for (int mt = 0; mt < 4; mt++)
#pragma unroll
        for (int nt = 0; nt < 4; nt++)
#pragma unroll
            for (int qq = 0; qq < 4; qq++) acc[mt][nt][qq] = 0.f;

    load_tileH(A, lda, bm, 0, smh, tid);
    load_tileH(B, ldb, bn, 0, smh + HTILE, tid);
    asm volatile("cp.async.commit_group;" ::: "memory");
    asm volatile("cp.async.wait_group 0;" ::: "memory");
    __syncthreads();

    const __half* sA = smh;
    const __half* sB = sA + HTILE;

#pragma unroll
    for (int kk = 0; kk < 32; kk += 16) {
        uint32_t afr[4][4];
#pragma unroll
        for (int mt = 0; mt < 4; mt++) {
            int r0 = warp_m * 64 + mt * 16;
            afr[mt][0] = *(const uint32_t*)&sA[(r0 + g) * HPAD + kk + 2 * t];
            afr[mt][1] = *(const uint32_t*)&sA[(r0 + 8 + g) * HPAD + kk + 2 * t];
            afr[mt][2] = *(const uint32_t*)&sA[(r0 + g) * HPAD + kk + 2 * t + 8];
            afr[mt][3] = *(const uint32_t*)&sA[(r0 + 8 + g) * HPAD + kk + 2 * t + 8];
        }
        uint32_t bfr[4][2];
#pragma unroll
        for (int nt = 0; nt < 4; nt++) {
            int n0 = warp_n * 32 + nt * 8;
            bfr[nt][0] = *(const uint32_t*)&sB[(n0 + g) * HPAD + kk + 2 * t];
            bfr[nt][1] = *(const uint32_t*)&sB[(n0 + g) * HPAD + kk + 2 * t + 8];
        }
#pragma unroll
        for (int mt = 0; mt < 4; mt++)
#pragma unroll
            for (int nt = 0; nt < 4; nt++)
                mma16(acc[mt][nt], afr[mt], bfr[nt]);
    }

#pragma unroll
    for (int mt = 0; mt < 4; mt++) {
        int row = bm + warp_m * 64 + mt * 16 + g;
#pragma unroll
        for (int nt = 0; nt < 4; nt++) {
            int col = bn + warp_n * 32 + nt * 8 + t * 2;
            float b0 = bias[col], b1 = bias[col + 1];
            float2 v0 = make_float2(acc[mt][nt][0] + b0, acc[mt][nt][1] + b1);
            float2 v1 = make_float2(acc[mt][nt][2] + b0, acc[mt][nt][3] + b1);
            v0.x = fmaxf(v0.x, 0.f) + log1pf(expf(-fabsf(v0.x)));
            v0.y = fmaxf(v0.y, 0.f) + log1pf(expf(-fabsf(v0.y)));
            v1.x = fmaxf(v1.x, 0.f) + log1pf(expf(-fabsf(v1.x)));
            v1.y = fmaxf(v1.y, 0.f) + log1pf(expf(-fabsf(v1.y)));
            *(float2*)(C + (size_t)row * ldc + col) = v0;
            *(float2*)(C + (size_t)(row + 8) * ldc + col) = v1;
        }
    }
}

// ================= xproj fp16 GEMM: 64x64 CTA tile, dual fp32+fp16 output ==========
#define XTILE (64 * HPAD)
#define XSTAGE (2 * XTILE)
#define XNSTAGE 3
#define XSMEM_BYTES (XNSTAGE * XSTAGE * 2)

__device__ __forceinline__ void load_tileH64(const __half* __restrict__ g, int ld,
                                             int row0, int k0, __half* s, int tid) {
#pragma unroll
    for (int i = 0; i < 2; i++) {
        int flat = i * 128 + tid;
        int r = flat >> 2;
        int c = flat & 3;
        const __half* gp = g + (size_t)(row0 + r) * ld + k0 + c * 8;
        cpa16(smem_u32(s + r * HPAD + c * 8), gp);
    }
}

__global__ void __launch_bounds__(128)
gemm_xproj_kernel(const __half* __restrict__ A, int lda,
                  const __half* __restrict__ B, int ldb,
                  float* __restrict__ C, __half* __restrict__ Ch, int ldc, int K)
{
    extern __shared__ __half smh[];
    int tid = threadIdx.x;
    int wid = tid >> 5, lane = tid & 31;
    int g = lane >> 2, t = lane & 3;
    int warp_m = wid >> 1;
    int warp_n = wid & 1;
    int bm = blockIdx.y * 64;
    int bn = 0;

    float acc[2][4][4];
#pragma unroll
    for (int mt = 0; mt < 2; mt++)
#pragma unroll
        for (int nt = 0; nt < 4; nt++)
#pragma unroll
            for (int qq = 0; qq < 4; qq++) acc[mt][nt][qq] = 0.f;

    int nk = K >> 5;

    load_tileH64(A, lda, bm, 0, smh, tid);
    load_tileH64(B, ldb, bn, 0, smh + XTILE, tid);
    asm volatile("cp.async.commit_group;" ::: "memory");
    load_tileH64(A, lda, bm, 32, smh + XSTAGE, tid);
    load_tileH64(B, ldb, bn, 32, smh + XSTAGE + XTILE, tid);
    asm volatile("cp.async.commit_group;" ::: "memory");

    for (int kc = 0; kc < nk; kc++) {
        if (kc + 2 < nk) {
            int nb = (kc + 2) % XNSTAGE;
            load_tileH64(A, lda, bm, (kc + 2) * 32, smh + nb * XSTAGE, tid);
            load_tileH64(B, ldb, bn, (kc + 2) * 32, smh + nb * XSTAGE + XTILE, tid);
            asm volatile("cp.async.commit_group;" ::: "memory");
            asm volatile("cp.async.wait_group 2;" ::: "memory");
        } else if (kc + 1 < nk) {
            asm volatile("cp.async.wait_group 1;" ::: "memory");
        } else {
            asm volatile("cp.async.wait_group 0;" ::: "memory");
        }
        __syncthreads();

        const __half* sA = smh + (kc % XNSTAGE) * XSTAGE;
        const __half* sB = sA + XTILE;

#pragma unroll
        for (int kk = 0; kk < 32; kk += 16) {
            uint32_t afr[2][4];
#pragma unroll
            for (int mt = 0; mt < 2; mt++) {
                int r0 = warp_m * 32 + mt * 16;
                afr[mt][0] = *(const uint32_t*)&sA[(r0 + g) * HPAD + kk + 2 * t];
                afr[mt][1] = *(const uint32_t*)&sA[(r0 + 8 + g) * HPAD + kk + 2 * t];
                afr[mt][2] = *(const uint32_t*)&sA[(r0 + g) * HPAD + kk + 2 * t + 8];
                afr[mt][3] = *(const uint32_t*)&sA[(r0 + 8 + g) * HPAD + kk + 2 * t + 8];
            }
            uint32_t bfr[4][2];
#pragma unroll
            for (int nt = 0; nt < 4; nt++) {
                int n0 = warp_n * 32 + nt * 8;
                bfr[nt][0] = *(const uint32_t*)&sB[(n0 + g) * HPAD + kk + 2 * t];
                bfr[nt][1] = *(const uint32_t*)&sB[(n0 + g) * HPAD + kk + 2 * t + 8];
            }
#pragma unroll
            for (int mt = 0; mt < 2; mt++)
#pragma unroll
                for (int nt = 0; nt < 4; nt++)
                    mma16(acc[mt][nt], afr[mt], bfr[nt]);
        }
        __syncthreads();
    }

#pragma unroll
    for (int mt = 0; mt < 2; mt++) {
        int row = bm + warp_m * 32 + mt * 16 + g;
#pragma unroll
        for (int nt = 0; nt < 4; nt++) {
            int col = warp_n * 32 + nt * 8 + t * 2;
            *(float2*)(C + (size_t)row * ldc + col) = make_float2(acc[mt][nt][0], acc[mt][nt][1]);
            *(float2*)(C + (size_t)(row + 8) * ldc + col) = make_float2(acc[mt][nt][2], acc[mt][nt][3]);
            __half2 h0 = __floats2half2_rn(acc[mt][nt][0], acc[mt][nt][1]);
            __half2 h1 = __floats2half2_rn(acc[mt][nt][2], acc[mt][nt][3]);
            *(__half2*)(Ch + (size_t)row * ldc + col) = h0;
            *(__half2*)(Ch + (size_t)(row + 8) * ldc + col) = h1;
        }
    }
}

// ---------------- generic tiled SGEMM (ip GEMM only) ----------------
#define BM 64
#define BN 64
#define BKK 16

template<int MODE>
__global__ void __launch_bounds__(256) gemm_tn_kernel(
    const float* __restrict__ A, int lda,
    const float* __restrict__ Bw, int ldb,
    const float* __restrict__ bias,
    float* __restrict__ C, int ldc,
    int M, int N, int K)
{
    __shared__ float As[BKK][BM + 4];
    __shared__ float Bs[BKK][BN + 4];

    int tid = threadIdx.x;
    int bm = blockIdx.y * BM;
    int bn = blockIdx.x * BN;

    int lrow = tid >> 2;
    int lk   = (tid & 3) * 4;
    int tr = (tid >> 4) * 4;
    int tc = (tid & 15) * 4;

    float acc[4][4];
#pragma unroll
    for (int i = 0; i < 4; i++)
#pragma unroll
        for (int j = 0; j < 4; j++) acc[i][j] = 0.f;

    const float* Aptr = A + (size_t)(bm + lrow) * lda + lk;
    const float* Bptr = Bw + (size_t)(bn + lrow) * ldb + lk;

    for (int k0 = 0; k0 < K; k0 += BKK) {
        float4 av = *(const float4*)Aptr;
        float4 bv = *(const float4*)Bptr;
        if (MODE == 3 && k0 == 0 && lk == 0) {
            av.x *= 0.3f; av.y *= 0.5f; av.z *= 0.9f;
        }
        Aptr += BKK;
        Bptr += BKK;
        As[lk + 0][lrow] = av.x; As[lk + 1][lrow] = av.y;
        As[lk + 2][lrow] = av.z; As[lk + 3][lrow] = av.w;
        Bs[lk + 0][lrow] = bv.x; Bs[lk + 1][lrow] = bv.y;
        Bs[lk + 2][lrow] = bv.z; Bs[lk + 3][lrow] = bv.w;
        __syncthreads();
#pragma unroll
        for (int k = 0; k < BKK; ++k) {
            float4 a4 = *(const float4*)&As[k][tr];
            float4 b4 = *(const float4*)&Bs[k][tc];
            float ar[4] = {a4.x, a4.y, a4.z, a4.w};
            float br[4] = {b4.x, b4.y, b4.z, b4.w};
#pragma unroll
            for (int i = 0; i < 4; ++i)
#pragma unroll
                for (int j = 0; j < 4; ++j)
                    acc[i][j] = fmaf(ar[i], br[j], acc[i][j]);
        }
        __syncthreads();
    }

#pragma unroll
    for (int i = 0; i < 4; ++i) {
        float* Cp = C + (size_t)(bm + tr + i) * ldc + (bn + tc);
        float vals[4];
#pragma unroll
        for (int j = 0; j < 4; ++j) {
            float v = acc[i][j];
            if (bias) v += bias[bn + tc + j];
            vals[j] = v;
        }
        float4 r; r.x = vals[0]; r.y = vals[1]; r.z = vals[2]; r.w = vals[3];
        *(float4*)Cp = r;
    }
}

// ---------------- rmsnorm -> fp16 output for MMA ----------------
__global__ void __launch_bounds__(128) rmsnorm_kernel(
    const float* __restrict__ h, const float* __restrict__ w, __half* __restrict__ out)
{
    int row = blockIdx.x;
    const float* hr = h + (size_t)row * HID;
    float v[4];
    float ss = 0.f;
#pragma unroll
    for (int i = 0; i < 4; i++) {
        v[i] = hr[threadIdx.x + i * 128];
        ss += v[i] * v[i];
    }
#pragma unroll
    for (int o = 16; o; o >>= 1) ss += __shfl_xor_sync(0xffffffffu, ss, o);
    __shared__ float red[4];
    if ((threadIdx.x & 31) == 0) red[threadIdx.x >> 5] = ss;
    __syncthreads();
    float tot = red[0] + red[1] + red[2] + red[3];
    float sc = rsqrtf(tot * (1.f / (float)HID) + 1e-5f);
#pragma unroll
    for (int i = 0; i < 4; i++) {
        int c = threadIdx.x + i * 128;
        out[(size_t)row * HID + c] = __float2half(v[i] * sc * w[c]);
    }
}

// ---------------- depthwise causal conv (K=4) + bias + silu, fp16 in/out ----------
__global__ void conv_silu_kernel(const __half* __restrict__ xz,
                                 const float* __restrict__ cw,
                                 const float* __restrict__ cb,
                                 __half* __restrict__ xssm_h)
{
    int idx = blockIdx.x * blockDim.x + threadIdx.x;
    int d = idx & (DI - 1);
    int bt = idx >> 10;
    int t = bt & (Tlen - 1);
    float w0 = cw[d * 4 + 0], w1 = cw[d * 4 + 1], w2 = cw[d * 4 + 2], w3 = cw[d * 4 + 3];
    const __half* col = xz + (size_t)bt * (2 * DI) + d;
    float acc = cb[d] + w3 * __half2float(col[0]);
    if (t >= 1) acc += w2 * __half2float(col[-(2 * DI)]);
    if (t >= 2) acc += w1 * __half2float(col[-(4 * DI)]);
    if (t >= 3) acc += w0 * __half2float(col[-(6 * DI)]);
    float sig = 1.f / (1.f + __expf(-acc));
    xssm_h[(size_t)bt * DI + d] = __float2half(acc * sig);
}

// ================= scan v4: 128-thread blocks, 16 d/block, 512 blocks ===============
#define SCH4 64
#define NCH4 (Tlen / SCH4)   // 16

__global__ void __launch_bounds__(128) scan4_kernel(
    const float* __restrict__ delta,
    const __half* __restrict__ xssm_h,
    const float* __restrict__ dbl,
    const __half* __restrict__ xz_h,
    const float* __restrict__ A_log,
    const float* __restrict__ Dp,
    __half* __restrict__ y)
{
    __shared__ float sd[2][SCH4][16];    // delta
    __shared__ float sbc[2][SCH4][32];   // B | C
    __shared__ __half sxh[2][SCH4][16];  // x
    __shared__ __half szh[2][SCH4][16];  // z
    __shared__ float sy[SCH4][20];       // raw yp (padded)

    int tid = threadIdx.x;
    int b   = blockIdx.x >> 6;
    int dt0 = (blockIdx.x & 63) << 4;

    int wid = tid >> 5, lane = tid & 31;
    int j   = lane & 7;
    int sub = lane >> 3;
    int dloc = wid * 4 + sub;
    int d = dt0 + dloc;

    float A0 = -expf(A_log[d * DS + 2 * j]);
    float A1 = -expf(A_log[d * DS + 2 * j + 1]);
    float h0 = 0.f, h1 = 0.f;

    int sr = tid >> 1;
    int sc = (tid & 1) * 8;
    float Dreg[8];
#pragma unroll
    for (int k = 0; k < 8; k++) Dreg[k] = Dp[dt0 + sc + k];

    size_t base_row = (size_t)b * Tlen;
    int dr = tid >> 1, dq = (tid & 1) * 8;

    {
#pragma unroll
        for (int i = 0; i < 2; i++) {
            int flat = i * 128 + tid;
            int r = flat >> 2, q = (flat & 3) * 4;
            cpa16(smem_u32(&sd[0][r][q]), delta + (base_row + r) * DI + dt0 + q);
        }
#pragma unroll
        for (int i = 0; i < 4; i++) {
            int flat = i * 128 + tid;
            int r = flat >> 3, q = (flat & 7) * 4;
            cpa16(smem_u32(&sbc[0][r][q]), dbl + (base_row + r) * 64 + 32 + q);
        }
        cpa16(smem_u32(&sxh[0][dr][dq]), xssm_h + (base_row + dr) * DI + dt0 + dq);
        cpa16(smem_u32(&szh[0][dr][dq]), xz_h + (base_row + dr) * (2 * DI) + DI + dt0 + dq);
        asm volatile("cp.async.commit_group;" ::: "memory");
    }

    for (int c = 0; c < NCH4; c++) {
        int buf = c & 1;
        __syncthreads();
        if (c + 1 < NCH4) {
            int nb = 1 - buf;
            size_t rb = base_row + (c + 1) * SCH4;
#pragma unroll
            for (int i = 0; i < 2; i++) {
                int flat = i * 128 + tid;
                int r = flat >> 2, q = (flat & 3) * 4;
                cpa16(smem_u32(&sd[nb][r][q]), delta + (rb + r) * DI + dt0 + q);
            }
#pragma unroll
            for (int i = 0; i < 4; i++) {
                int flat = i * 128 + tid;
                int r = flat >> 3, q = (flat & 7) * 4;
                cpa16(smem_u32(&sbc[nb][r][q]), dbl + (rb + r) * 64 + 32 + q);
            }
            cpa16(smem_u32(&sxh[nb][dr][dq]), xssm_h + (rb + dr) * DI + dt0 + dq);
            cpa16(smem_u32(&szh[nb][dr][dq]), xz_h + (rb + dr) * (2 * DI) + DI + dt0 + dq);
            asm volatile("cp.async.commit_group;" ::: "memory");
            asm volatile("cp.async.wait_group 1;" ::: "memory");
        } else {
            asm volatile("cp.async.wait_group 0;" ::: "memory");
        }
        __syncthreads();

#pragma unroll 4
        for (int tt = 0; tt < SCH4; tt++) {
            float dtv = sd[buf][tt][dloc];
            float dtx = dtv * __half2float(sxh[buf][tt][dloc]);
            float2 B2 = *(const float2*)&sbc[buf][tt][2 * j];
            float2 C2 = *(const float2*)&sbc[buf][tt][16 + 2 * j];
            h0 = fmaf(h0, __expf(dtv * A0), dtx * B2.x);
            h1 = fmaf(h1, __expf(dtv * A1), dtx * B2.y);
            float yp = fmaf(h1, C2.y, h0 * C2.x);
            yp += __shfl_xor_sync(0xffffffffu, yp, 4, 32);
            yp += __shfl_xor_sync(0xffffffffu, yp, 2, 32);
            yp += __shfl_xor_sync(0xffffffffu, yp, 1, 32);
            if (j == 0) sy[tt][dloc] = yp;
        }
        __syncthreads();

        {
            size_t ro = base_row + c * SCH4 + sr;
            __half2 hh[4];
#pragma unroll
            for (int k2 = 0; k2 < 4; k2++) {
                float r0, r1;
#pragma unroll
                for (int e = 0; e < 2; e++) {
                    int col = sc + k2 * 2 + e;
                    float yp = sy[sr][col];
                    float xv = __half2float(sxh[buf][sr][col]);
                    float zv = __half2float(szh[buf][sr][col]);
                    float szl = zv / (1.f + __expf(-zv));
                    float yv = (yp + xv * Dreg[k2 * 2 + e]) * szl;
                    if (e == 0) r0 = yv; else r1 = yv;
                }
                hh[k2] = __floats2half2_rn(r0, r1);
            }
            uint4 u;
            u.x = *(const uint32_t*)&hh[0];
            u.y = *(const uint32_t*)&hh[1];
            u.z = *(const uint32_t*)&hh[2];
            u.w = *(const uint32_t*)&hh[3];
            *(uint4*)(y + ro * DI + dt0 + sc) = u;
        }
    }
}

// ---------------- final FC on last token ----------------
__global__ void fc_kernel(const float* __restrict__ h, const float* __restrict__ fc_w,
                          const float* __restrict__ fc_b, float* __restrict__ out)
{
    int idx = blockIdx.x * blockDim.x + threadIdx.x;
    if (idx >= Bsz * Fdim) return;
    int b = idx / Fdim, f = idx % Fdim;
    const float* hr = h + ((size_t)b * Tlen + (Tlen - 1)) * HID;
    const float* wr = fc_w + (size_t)f * HID;
    float acc = fc_b[f];
    for (int k = 0; k < HID; k += 4) {
        float4 hv = *(const float4*)(hr + k);
        float4 wv = *(const float4*)(wr + k);
        acc += hv.x * wv.x + hv.y * wv.y + hv.z * wv.z + hv.w * wv.w;
    }
    out[idx] = acc;
}

// ---------------- launcher ----------------
extern "C" void kernel_launch(void* const* d_in, const int* in_sizes, int n_in,
                              void* d_out, int out_size)
{
    const float* x        = (const float*)d_in[0];
    const float* ip_w     = (const float*)d_in[1];
    const float* ip_b     = (const float*)d_in[2];
    const float* norm_w   = (const float*)d_in[3];
    const float* inp_w    = (const float*)d_in[4];
    const float* conv_w   = (const float*)d_in[5];
    const float* conv_b   = (const float*)d_in[6];
    const float* xproj_w  = (const float*)d_in[7];
    const float* dtproj_w = (const float*)d_in[8];
    const float* dtproj_b = (const float*)d_in[9];
    const float* A_log    = (const float*)d_in[10];
    const float* Dvec     = (const float*)d_in[11];
    const float* outp_w   = (const float*)d_in[12];
    const float* fc_w     = (const float*)d_in[13];
    const float* fc_b     = (const float*)d_in[14];

    float *h, *dbl, *delta;
    __half *hn_h, *y_h, *wi_h, *wo_h, *xz_h, *xssm_h, *dbl_h, *xpw_h, *dpw_h;
    cudaGetSymbolAddress((void**)&h, g_h);
    cudaGetSymbolAddress((void**)&hn_h, g_hn_h);
    cudaGetSymbolAddress((void**)&xz_h, g_xz_h);
    cudaGetSymbolAddress((void**)&xssm_h, g_xssm_h);
    cudaGetSymbolAddress((void**)&dbl, g_dbl);
    cudaGetSymbolAddress((void**)&dbl_h, g_dbl_h);
    cudaGetSymbolAddress((void**)&delta, g_delta);
    cudaGetSymbolAddress((void**)&y_h, g_y_h);
    cudaGetSymbolAddress((void**)&wi_h, g_wi_h);
    cudaGetSymbolAddress((void**)&wo_h, g_wo_h);
    cudaGetSymbolAddress((void**)&xpw_h, g_xpw_h);
    cudaGetSymbolAddress((void**)&dpw_h, g_dpw_h);

    static int attr_done = 0;
    if (!attr_done) {
        cudaFuncSetAttribute(gemm_hmma64_kernel<0>, cudaFuncAttributeMaxDynamicSharedMemorySize, H2SMEM_BYTES);
        cudaFuncSetAttribute(gemm_hmma64_kernel<1>, cudaFuncAttributeMaxDynamicSharedMemorySize, H2SMEM_BYTES);
        cudaFuncSetAttribute(gemm_dtproj_kernel, cudaFuncAttributeMaxDynamicSharedMemorySize, HSMEM_BYTES);
        cudaFuncSetAttribute(gemm_xproj_kernel, cudaFuncAttributeMaxDynamicSharedMemorySize, XSMEM_BYTES);
        attr_done = 1;
    }

    // (1) convert ALL weights to fp16 (single launch)
    f2h_all_kernel<<<(N_ALLW + 255) / 256, 256>>>(
        inp_w, outp_w, xproj_w, dtproj_w, wi_h, wo_h, xpw_h, dpw_h);

    // (2) h = scaled_x @ ip_w^T + ip_b
    gemm_tn_kernel<3><<<dim3(HID / BN, MT / BM), 256>>>(
        x, IN_DIM, ip_w, IN_DIM, ip_b, h, HID, MT, HID, IN_DIM);

    // (3) hn = rmsnorm(h) * nw  -> fp16   (layer 0)
    rmsnorm_kernel<<<MT, 128>>>(h, norm_w, hn_h);

    // (4) xz = hn @ inp_w^T  — fp16 mma v2 (512 thr), fp16 output   [ncu capture slot]
    gemm_hmma64_kernel<0><<<dim3((2 * DI) / 128, MT / 128), 512, H2SMEM_BYTES>>>(
        hn_h, HID, wi_h, HID, nullptr, xz_h, 2 * DI, HID);

    for (int l = 0; l < 2; l++) {
        const float* cw  = conv_w + (size_t)l * DI * 4;
        const float* cb  = conv_b + (size_t)l * DI;
        const float* dpb = dtproj_b + (size_t)l * DI;
        const float* Al  = A_log + (size_t)l * DI * DS;
        const float* Dl  = Dvec + (size_t)l * DI;
        const __half* wol  = wo_h + (size_t)l * HID * DI;
        const __half* xpwl = xpw_h + (size_t)l * 64 * DI;
        const __half* dpwl = dpw_h + (size_t)l * DI * DTR;

        if (l > 0) {
            rmsnorm_kernel<<<MT, 128>>>(h, norm_w + l * HID, hn_h);
            gemm_hmma64_kernel<0><<<dim3((2 * DI) / 128, MT / 128), 512, H2SMEM_BYTES>>>(
                hn_h, HID, wi_h + (size_t)l * 2 * DI * HID, HID, nullptr, xz_h, 2 * DI, HID);
        }

        // depthwise conv + silu -> xssm_h (fp16)
        conv_silu_kernel<<<(MT * DI) / 256, 256>>>(xz_h, cw, cb, xssm_h);

        // dbl = xssm @ xproj_w^T  — fp16 mma, dual fp32+fp16 output
        gemm_xproj_kernel<<<dim3(1, MT / 64), 128, XSMEM_BYTES>>>(
            xssm_h, DI, xpwl, DI, dbl, dbl_h, 64, DI);

        // delta = softplus(dt_raw @ dtproj_w^T + dtproj_b)  (K=32) — fp16 mma
        gemm_dtproj_kernel<<<dim3(DI / 128, MT / 128), 256, HSMEM_BYTES>>>(
            dbl_h, 64, dpwl, DTR, dpb, delta, DI);

        // selective scan v4 -> y (fp16)
        scan4_kernel<<<Bsz * (DI / 16), 128>>>(
            delta, xssm_h, dbl, xz_h, Al, Dl, y_h);

        // h += y @ outp_w^T  — fp16 mma v2, fp32 residual add
        gemm_hmma64_kernel<1><<<dim3(HID / 128, MT / 128), 512, H2SMEM_BYTES>>>(
            y_h, DI, wol, DI, h, nullptr, HID, DI);
    }

    // out = h[:, -1, :] @ fc_w^T + fc_b
    fc_kernel<<<3, 256>>>(h, fc_w, fc_b, (float*)d_out);
}